// round 16
// baseline (speedup 1.0000x reference)
#include <cuda_runtime.h>
#include <cuda_fp16.h>
#include <stdint.h>

// Problem dims (fixed): B=4, S=2048, D=1024, H=16, HD=64
#define LOG2E 1.4426950408889634f
#define SCL   (0.125f * 1.4426950408889634f)   // 1/sqrt(64) * log2(e)

// ---------------- device scratch (static: allocation-free at launch) -------
__device__ __half g_Xh[8192 * 1024];          // hidden in fp16        (16 MB)
__device__ __half g_Wh[3][1024 * 1024];       // Wq/Wk/Wv in fp16      ( 6 MB)
__device__ __half g_Q [64 * 2048 * 64];       // Q  [bh][s][hd]        (16 MB)
__device__ __half g_K [64 * 2048 * 64];       // K  [bh][s][hd]        (16 MB)
__device__ __half g_Vt[64 * 64 * 2048];       // V^T [bh][hd][s]       (16 MB)

// ---------------- helpers ----------------------------------------------------
__device__ __forceinline__ uint32_t smem_u32(const void* p) {
    return (uint32_t)__cvta_generic_to_shared(p);
}
__device__ __forceinline__ void ldm4(uint32_t* r, uint32_t a) {
    asm volatile("ldmatrix.sync.aligned.m8n8.x4.shared.b16 {%0,%1,%2,%3}, [%4];"
                 : "=r"(r[0]), "=r"(r[1]), "=r"(r[2]), "=r"(r[3]) : "r"(a));
}
__device__ __forceinline__ void mma16816(float* c, const uint32_t* a, const uint32_t* b) {
    asm volatile(
        "mma.sync.aligned.m16n8k16.row.col.f32.f16.f16.f32 "
        "{%0,%1,%2,%3}, {%4,%5,%6,%7}, {%8,%9}, {%0,%1,%2,%3};"
        : "+f"(c[0]), "+f"(c[1]), "+f"(c[2]), "+f"(c[3])
        : "r"(a[0]), "r"(a[1]), "r"(a[2]), "r"(a[3]), "r"(b[0]), "r"(b[1]));
}
__device__ __forceinline__ void cpa16(uint32_t dst, const void* src) {
    asm volatile("cp.async.cg.shared.global [%0], [%1], 16;" :: "r"(dst), "l"(src));
}
#define CP_COMMIT() asm volatile("cp.async.commit_group;")
#define CP_WAIT(n)  asm volatile("cp.async.wait_group %0;" :: "n"(n))

__device__ __forceinline__ uint32_t h2ex2(float a, float b, __half2 clamp) {
    __half2 h = __hmin2(__floats2half2_rn(a, b), clamp);
    uint32_t r, x = *reinterpret_cast<uint32_t*>(&h);
    asm volatile("ex2.approx.f16x2 %0, %1;" : "=r"(r) : "r"(x));
    return r;
}

// ---------------- fp32 -> fp16 convert (X + all 3 W in one launch) ----------
__global__ void cvt_all(const float4* __restrict__ x,
                        const float4* __restrict__ wq,
                        const float4* __restrict__ wk,
                        const float4* __restrict__ wv) {
    int bid = blockIdx.x;
    const float4* src;
    __half2* dst;
    int i;
    if (bid < 8192) {                       // X: 2097152 float4s
        src = x; dst = (__half2*)g_Xh;
        i = bid * 256 + threadIdx.x;
    } else {                                // W[z]: 262144 float4s each
        int r = bid - 8192;
        int z = r >> 10;
        src = (z == 0) ? wq : (z == 1) ? wk : wv;
        dst = (__half2*)g_Wh[z];
        i = (r & 1023) * 256 + threadIdx.x;
    }
    float4 v = src[i];
    dst[2 * i + 0] = __floats2half2_rn(v.x, v.y);
    dst[2 * i + 1] = __floats2half2_rn(v.z, v.w);
}

// ---------------- fused QKV projection (unchanged winner) -------------------
// BK=64, CTA tile 128x128, 8 warps (warp tile 64x32), occupancy 2.
// 3-stage cp.async ring with wait_group 1.
// smem: A stages [3][128][72]h at 0 (55296 B), B stages at 55296. 110592 B.
#define QKV_SMEM 110592
__global__ __launch_bounds__(256, 2) void qkv_gemm(const float* __restrict__ bq,
                                                   const float* __restrict__ bk,
                                                   const float* __restrict__ bv) {
    extern __shared__ char qsm[];

    const int z  = blockIdx.z;
    const __half* W    = g_Wh[z];
    const float*  bias = (z == 0) ? bq : (z == 1) ? bk : bv;
    const int m0 = blockIdx.y * 128;
    const int n0 = blockIdx.x * 128;

    const int t    = threadIdx.x;
    const int warp = t >> 5, lane = t & 31;
    const int wm = warp & 1, wn = warp >> 1;

    auto load_st = [&](int st, int kb) {
#pragma unroll
        for (int i = 0; i < 4; i++) {
            int idx = t + i * 256;              // 1024 chunks of 16B per tile
            int row = idx >> 3, c = idx & 7;
            cpa16(smem_u32(qsm + st * 18432 + row * 144 + c * 16),
                  g_Xh + (size_t)(m0 + row) * 1024 + kb * 64 + c * 8);
            cpa16(smem_u32(qsm + 55296 + st * 18432 + row * 144 + c * 16),
                  W + (size_t)(n0 + row) * 1024 + kb * 64 + c * 8);
        }
    };

    float acc[4][4][4];
#pragma unroll
    for (int i = 0; i < 4; i++)
#pragma unroll
        for (int j = 0; j < 4; j++)
#pragma unroll
            for (int k = 0; k < 4; k++) acc[i][j][k] = 0.f;

    const uint32_t aOff = (uint32_t)(wm * 64 + (lane & 15)) * 144 + (lane >> 4) * 16;
    const uint32_t bOff = (uint32_t)(wn * 32 + (lane & 7) + ((lane >> 4) & 1) * 8) * 144
                        + ((lane >> 3) & 1) * 16;

    load_st(0, 0);
    CP_COMMIT();
    load_st(1, 1);
    CP_COMMIT();

    int st = 0;
    for (int kb = 0; kb < 16; kb++) {
        CP_WAIT(1);
        __syncthreads();
        if (kb + 2 < 16) load_st((kb + 2) % 3, kb + 2);
        CP_COMMIT();

        const uint32_t aAddr = smem_u32(qsm) + st * 18432 + aOff;
        const uint32_t bAddr = smem_u32(qsm) + 55296 + st * 18432 + bOff;
        st = (st == 2) ? 0 : st + 1;
#pragma unroll
        for (int kc = 0; kc < 4; kc++) {
            uint32_t a[4][4], b[2][4];
#pragma unroll
            for (int mt = 0; mt < 4; mt++) ldm4(a[mt], aAddr + kc * 32 + mt * 16 * 144);
#pragma unroll
            for (int np = 0; np < 2; np++) ldm4(b[np], bAddr + kc * 32 + np * 16 * 144);
#pragma unroll
            for (int mt = 0; mt < 4; mt++)
#pragma unroll
                for (int nt = 0; nt < 4; nt++)
                    mma16816(acc[mt][nt], a[mt], b[nt >> 1] + (nt & 1) * 2);
        }
    }

    // epilogue: bias + store into head-major scratch (fp16)
#pragma unroll
    for (int mt = 0; mt < 4; mt++) {
        int m  = m0 + wm * 64 + mt * 16 + (lane >> 2);
        int bb = m >> 11;
        int s  = m & 2047;
#pragma unroll
        for (int nt = 0; nt < 4; nt++) {
            int n  = n0 + wn * 32 + nt * 8 + (lane & 3) * 2;
            int h  = n >> 6, hd = n & 63;
            int bh = bb * 16 + h;
            float bs0 = bias[n], bs1 = bias[n + 1];
            float v00 = acc[mt][nt][0] + bs0, v01 = acc[mt][nt][1] + bs1;
            float v10 = acc[mt][nt][2] + bs0, v11 = acc[mt][nt][3] + bs1;
            if (z < 2) {
                __half* dst = (z == 0) ? g_Q : g_K;
                *(__half2*)&dst[((size_t)bh * 2048 + s    ) * 64 + hd] = __floats2half2_rn(v00, v01);
                *(__half2*)&dst[((size_t)bh * 2048 + s + 8) * 64 + hd] = __floats2half2_rn(v10, v11);
            } else {
                g_Vt[((size_t)bh * 64 + hd    ) * 2048 + s    ] = __float2half_rn(v00);
                g_Vt[((size_t)bh * 64 + hd + 1) * 2048 + s    ] = __float2half_rn(v01);
                g_Vt[((size_t)bh * 64 + hd    ) * 2048 + s + 8] = __float2half_rn(v10);
                g_Vt[((size_t)bh * 64 + hd + 1) * 2048 + s + 8] = __float2half_rn(v11);
            }
        }
    }
}

// ---------------- FlashAttention (software-pipelined 16-key chunks) ---------
// R14 staging (128-key stages, smem mask, 4 warps x 32 q-rows) with the inner
// compute restructured as an 8-chunk software pipeline: score MMA of chunk
// cc+1 is issued BEFORE softmax+PV of chunk cc (independent registers, two
// ping-pong 16-reg score buffers), so tensor-pipe work of the next chunk
// overlaps the FMA/MUFU softmax of the current one.
// Identical arithmetic & accumulation order -> identical rel_err.
// smem layout (bytes):
//   Qs [128][72] half  : 0      .. 18432
//   Ks [2][128][72]    : 18432  .. 55296   (stage = 18432)
//   Vs [2][64][136]    : 55296  .. 90112   (stage = 17408, 272B rows)
//   maskSm [2048] f32  : 90112  .. 98304
#define ATTN_SMEM 98304
__global__ __launch_bounds__(128, 2) void attn_kernel(const float* __restrict__ mask,
                                                      float* __restrict__ out) {
    extern __shared__ char sm[];
    __half (*Qs)[72] = (__half(*)[72])sm;
    char* ksBase = sm + 18432;
    char* vsBase = sm + 55296;
    float* maskSm = (float*)(sm + 90112);

    const int bh = blockIdx.y;
    const int q0 = blockIdx.x * 128;
    const int b  = bh >> 4, h = bh & 15;
    const int t = threadIdx.x, warp = t >> 5, lane = t & 31;
    const __half2 clamp14 = __floats2half2_rn(14.f, 14.f);

    // stage loader: 128-key K tile (128x72h rows) + V^T tile (64x136h rows)
    auto load_kv = [&](int st, int k0) {
#pragma unroll
        for (int i = 0; i < 8; i++) {
            int idx = t + i * 128;           // K: 1024 chunks of 16B
            int row = idx >> 3, cb = idx & 7;
            cpa16(smem_u32(ksBase + st * 18432 + row * 144 + cb * 16),
                  &g_K[((size_t)bh * 2048 + k0 + row) * 64 + cb * 8]);
        }
#pragma unroll
        for (int i = 0; i < 8; i++) {
            int idx = t + i * 128;           // V: 1024 chunks of 16B
            int row = idx >> 4, cb = idx & 15;
            cpa16(smem_u32(vsBase + st * 17408 + row * 272 + cb * 16),
                  &g_Vt[((size_t)bh * 64 + row) * 2048 + k0 + cb * 8]);
        }
    };

    load_kv(0, 0);
    CP_COMMIT();

    // one-time mask preload (scaled by LOG2E); LDGs overlap Q tile loads
#pragma unroll
    for (int i = 0; i < 16; i++)
        maskSm[t + i * 128] = mask[b * 2048 + t + i * 128] * LOG2E;

#pragma unroll
    for (int i = 0; i < 8; i++) {
        int idx = t + i * 128;              // 1024 chunks for the 128x64 Q tile
        int row = idx >> 3, c8 = (idx & 7) * 8;
        *(uint4*)&Qs[row][c8] =
            *(const uint4*)&g_Q[((size_t)bh * 2048 + q0 + row) * 64 + c8];
    }
    __syncthreads();

    // Q fragments: 2 m-tiles x 4 k-chunks
    uint32_t qa[2][4][4];
#pragma unroll
    for (int mt = 0; mt < 2; mt++) {
        uint32_t qAddr = smem_u32(&Qs[warp * 32 + mt * 16 + (lane & 15)][(lane >> 4) * 8]);
#pragma unroll
        for (int ks = 0; ks < 4; ks++) ldm4(qa[mt][ks], qAddr + ks * 32);
    }

    const uint32_t kOff = ((lane & 7) + ((lane >> 4) & 1) * 8) * 144 + ((lane >> 3) & 1) * 16;
    const uint32_t vOff = ((lane & 7) + ((lane >> 4) & 1) * 8) * 272 + ((lane >> 3) & 1) * 16;
    const uint32_t kA0 = smem_u32(ksBase) + kOff;
    const uint32_t vA0 = smem_u32(vsBase) + vOff;

    float o[2][8][4];
#pragma unroll
    for (int mt = 0; mt < 2; mt++)
#pragma unroll
        for (int i = 0; i < 8; i++)
#pragma unroll
            for (int j = 0; j < 4; j++) o[mt][i][j] = 0.f;
    float l00 = 0.f, l01 = 0.f, l10 = 0.f, l11 = 0.f;

    for (int kt = 0; kt < 16; kt++) {
        CP_WAIT(0);                    // stage kt resident
        __syncthreads();               // stage kt-1 fully consumed by all warps
        if (kt + 1 < 16) load_kv((kt + 1) & 1, (kt + 1) * 128);
        CP_COMMIT();

        const int stg = kt & 1;
        const uint32_t kB = kA0 + stg * 18432;   // chunk cc: +cc*2304 (16 rows)
        const uint32_t vB = vA0 + stg * 17408;   // chunk cc: +cc*32   (16 keys)
        const float* mk = maskSm + kt * 128;

        // score MMA for 16-key chunk cc into s[2][2][4]
        auto chunk_scores = [&](int cc, float s[2][2][4]) {
#pragma unroll
            for (int mt = 0; mt < 2; mt++)
#pragma unroll
                for (int u = 0; u < 2; u++)
#pragma unroll
                    for (int j = 0; j < 4; j++) s[mt][u][j] = 0.f;
#pragma unroll
            for (int ks = 0; ks < 4; ks++) {
                uint32_t kf[4];
                ldm4(kf, kB + cc * 2304 + ks * 32);
#pragma unroll
                for (int mt = 0; mt < 2; mt++) {
                    mma16816(s[mt][0], qa[mt][ks], kf);
                    mma16816(s[mt][1], qa[mt][ks], kf + 2);
                }
            }
        };

        // softmax + PV for chunk cc from s
        auto chunk_spv = [&](int cc, float s[2][2][4]) {
            uint32_t vf[4][4];
#pragma unroll
            for (int hp = 0; hp < 4; hp++)
                ldm4(vf[hp], vB + hp * 16 * 272 + cc * 32);

            uint32_t ph[2][4];
#pragma unroll
            for (int mt = 0; mt < 2; mt++) {
                float lp0 = 0.f, lp1 = 0.f;
#pragma unroll
                for (int u = 0; u < 2; u++) {
                    int key = cc * 16 + u * 8 + (lane & 3) * 2;
                    float mk0v = mk[key], mk1v = mk[key + 1];
                    float a0 = fmaf(s[mt][u][0], SCL, mk0v);
                    float a1 = fmaf(s[mt][u][1], SCL, mk1v);
                    float a2 = fmaf(s[mt][u][2], SCL, mk0v);
                    float a3 = fmaf(s[mt][u][3], SCL, mk1v);
                    ph[mt][2*u    ] = h2ex2(a0, a1, clamp14);
                    ph[mt][2*u + 1] = h2ex2(a2, a3, clamp14);
                    float2 f0 = __half22float2(*reinterpret_cast<__half2*>(&ph[mt][2*u]));
                    float2 f1 = __half22float2(*reinterpret_cast<__half2*>(&ph[mt][2*u+1]));
                    lp0 += f0.x + f0.y;
                    lp1 += f1.x + f1.y;
                }
                if (mt == 0) { l00 += lp0; l01 += lp1; }
                else         { l10 += lp0; l11 += lp1; }
            }
#pragma unroll
            for (int hp = 0; hp < 4; hp++)
#pragma unroll
                for (int mt = 0; mt < 2; mt++) {
                    mma16816(o[mt][2*hp    ], ph[mt], vf[hp]);
                    mma16816(o[mt][2*hp + 1], ph[mt], vf[hp] + 2);
                }
        };

        // 8-chunk software pipeline: scores(cc+1) issued before softmax+PV(cc)
        float sA[2][2][4], sB[2][2][4];
        chunk_scores(0, sA);
#pragma unroll
        for (int cc = 0; cc < 8; cc++) {
            if (cc + 1 < 8) chunk_scores(cc + 1, (cc & 1) ? sA : sB);
            chunk_spv(cc, (cc & 1) ? sB : sA);
        }
    }

    // epilogue: one cross-lane reduction, normalize, store fp32 [B,S,D]
    l00 += __shfl_xor_sync(0xffffffffu, l00, 1);
    l00 += __shfl_xor_sync(0xffffffffu, l00, 2);
    l01 += __shfl_xor_sync(0xffffffffu, l01, 1);
    l01 += __shfl_xor_sync(0xffffffffu, l01, 2);
    l10 += __shfl_xor_sync(0xffffffffu, l10, 1);
    l10 += __shfl_xor_sync(0xffffffffu, l10, 2);
    l11 += __shfl_xor_sync(0xffffffffu, l11, 1);
    l11 += __shfl_xor_sync(0xffffffffu, l11, 2);
    const int cb = h * 64 + (lane & 3) * 2;
#pragma unroll
    for (int mt = 0; mt < 2; mt++) {
        float rl0 = 1.f / (mt ? l10 : l00);
        float rl1 = 1.f / (mt ? l11 : l01);
        int s0 = q0 + warp * 32 + mt * 16 + (lane >> 2);
#pragma unroll
        for (int ht = 0; ht < 8; ht++) {
            int c = cb + ht * 8;
            float2 v0 = make_float2(o[mt][ht][0] * rl0, o[mt][ht][1] * rl0);
            float2 v1 = make_float2(o[mt][ht][2] * rl1, o[mt][ht][3] * rl1);
            *(float2*)&out[((size_t)b * 2048 + s0    ) * 1024 + c] = v0;
            *(float2*)&out[((size_t)b * 2048 + s0 + 8) * 1024 + c] = v1;
        }
    }
}

// ---------------- launch -----------------------------------------------------
extern "C" void kernel_launch(void* const* d_in, const int* in_sizes, int n_in,
                              void* d_out, int out_size) {
    const float* hidden = (const float*)d_in[0];
    const float* mask   = (const float*)d_in[1];
    const float* Wq     = (const float*)d_in[2];
    const float* bq     = (const float*)d_in[3];
    const float* Wk     = (const float*)d_in[4];
    const float* bk     = (const float*)d_in[5];
    const float* Wv     = (const float*)d_in[6];
    const float* bv     = (const float*)d_in[7];
    float* out = (float*)d_out;

    cudaFuncSetAttribute(qkv_gemm, cudaFuncAttributeMaxDynamicSharedMemorySize, QKV_SMEM);
    cudaFuncSetAttribute(attn_kernel, cudaFuncAttributeMaxDynamicSharedMemorySize, ATTN_SMEM);

    cvt_all<<<11264, 256>>>((const float4*)hidden, (const float4*)Wq,
                            (const float4*)Wk, (const float4*)Wv);

    dim3 g1(8, 64, 3);      // N-blocks, M-blocks, {Q,K,V}
    qkv_gemm<<<g1, 256, QKV_SMEM>>>(bq, bk, bv);

    dim3 g2(16, 64);        // q-tiles (128 rows), B*H
    attn_kernel<<<g2, 128, ATTN_SMEM>>>(mask, out);
}

// round 17
// speedup vs baseline: 1.0179x; 1.0179x over previous
#include <cuda_runtime.h>
#include <cuda_fp16.h>
#include <stdint.h>

// Problem dims (fixed): B=4, S=2048, D=1024, H=16, HD=64
#define LOG2E 1.4426950408889634f
#define SCL   (0.125f * 1.4426950408889634f)   // 1/sqrt(64) * log2(e)

// ---------------- device scratch (static: allocation-free at launch) -------
__device__ __half g_Xh[8192 * 1024];          // hidden in fp16        (16 MB)
__device__ __half g_Wh[3][1024 * 1024];       // Wq/Wk/Wv in fp16      ( 6 MB)
__device__ __half g_Q [64 * 2048 * 64];       // Q  [bh][s][hd]        (16 MB)
__device__ __half g_K [64 * 2048 * 64];       // K  [bh][s][hd]        (16 MB)
__device__ __half g_Vt[64 * 64 * 2048];       // V^T [bh][hd][s]       (16 MB)

// ---------------- helpers ----------------------------------------------------
__device__ __forceinline__ uint32_t smem_u32(const void* p) {
    return (uint32_t)__cvta_generic_to_shared(p);
}
__device__ __forceinline__ void ldm4(uint32_t* r, uint32_t a) {
    asm volatile("ldmatrix.sync.aligned.m8n8.x4.shared.b16 {%0,%1,%2,%3}, [%4];"
                 : "=r"(r[0]), "=r"(r[1]), "=r"(r[2]), "=r"(r[3]) : "r"(a));
}
// fp32-accum HMMA (PV + projections)
__device__ __forceinline__ void mma16816(float* c, const uint32_t* a, const uint32_t* b) {
    asm volatile(
        "mma.sync.aligned.m16n8k16.row.col.f32.f16.f16.f32 "
        "{%0,%1,%2,%3}, {%4,%5,%6,%7}, {%8,%9}, {%0,%1,%2,%3};"
        : "+f"(c[0]), "+f"(c[1]), "+f"(c[2]), "+f"(c[3])
        : "r"(a[0]), "r"(a[1]), "r"(a[2]), "r"(a[3]), "r"(b[0]), "r"(b[1]));
}
// fp16-accum HMMA (2x rate) — scores only. C = 2 b32 regs of packed half2:
// c[0] = (row, col|col+1), c[1] = (row+8, col|col+1) — same layout as ph.
__device__ __forceinline__ void mma16816h(uint32_t* c, const uint32_t* a, const uint32_t* b) {
    asm volatile(
        "mma.sync.aligned.m16n8k16.row.col.f16.f16.f16.f16 "
        "{%0,%1}, {%2,%3,%4,%5}, {%6,%7}, {%0,%1};"
        : "+r"(c[0]), "+r"(c[1])
        : "r"(a[0]), "r"(a[1]), "r"(a[2]), "r"(a[3]), "r"(b[0]), "r"(b[1]));
}
__device__ __forceinline__ void cpa16(uint32_t dst, const void* src) {
    asm volatile("cp.async.cg.shared.global [%0], [%1], 16;" :: "r"(dst), "l"(src));
}
#define CP_COMMIT() asm volatile("cp.async.commit_group;")
#define CP_WAIT(n)  asm volatile("cp.async.wait_group %0;" :: "n"(n))

// p = ex2(min(s*scl + mk, clamp)) entirely in half2 (one HFMA2 + HMIN2 + MUFU)
__device__ __forceinline__ uint32_t softmax2(uint32_t s, uint32_t scl2, uint32_t mk2,
                                             __half2 clamp) {
    uint32_t f, r;
    asm volatile("fma.rn.f16x2 %0, %1, %2, %3;" : "=r"(f) : "r"(s), "r"(scl2), "r"(mk2));
    __half2 hc = __hmin2(*reinterpret_cast<__half2*>(&f), clamp);
    uint32_t x = *reinterpret_cast<uint32_t*>(&hc);
    asm volatile("ex2.approx.f16x2 %0, %1;" : "=r"(r) : "r"(x));
    return r;
}

// ---------------- fp32 -> fp16 convert (X + all 3 W in one launch) ----------
__global__ void cvt_all(const float4* __restrict__ x,
                        const float4* __restrict__ wq,
                        const float4* __restrict__ wk,
                        const float4* __restrict__ wv) {
    int bid = blockIdx.x;
    const float4* src;
    __half2* dst;
    int i;
    if (bid < 8192) {                       // X: 2097152 float4s
        src = x; dst = (__half2*)g_Xh;
        i = bid * 256 + threadIdx.x;
    } else {                                // W[z]: 262144 float4s each
        int r = bid - 8192;
        int z = r >> 10;
        src = (z == 0) ? wq : (z == 1) ? wk : wv;
        dst = (__half2*)g_Wh[z];
        i = (r & 1023) * 256 + threadIdx.x;
    }
    float4 v = src[i];
    dst[2 * i + 0] = __floats2half2_rn(v.x, v.y);
    dst[2 * i + 1] = __floats2half2_rn(v.z, v.w);
}

// ---------------- fused QKV projection (unchanged winner) -------------------
// BK=64, CTA tile 128x128, 8 warps (warp tile 64x32), occupancy 2.
// 3-stage cp.async ring with wait_group 1.
// smem: A stages [3][128][72]h at 0 (55296 B), B stages at 55296. 110592 B.
#define QKV_SMEM 110592
__global__ __launch_bounds__(256, 2) void qkv_gemm(const float* __restrict__ bq,
                                                   const float* __restrict__ bk,
                                                   const float* __restrict__ bv) {
    extern __shared__ char qsm[];

    const int z  = blockIdx.z;
    const __half* W    = g_Wh[z];
    const float*  bias = (z == 0) ? bq : (z == 1) ? bk : bv;
    const int m0 = blockIdx.y * 128;
    const int n0 = blockIdx.x * 128;

    const int t    = threadIdx.x;
    const int warp = t >> 5, lane = t & 31;
    const int wm = warp & 1, wn = warp >> 1;

    auto load_st = [&](int st, int kb) {
#pragma unroll
        for (int i = 0; i < 4; i++) {
            int idx = t + i * 256;              // 1024 chunks of 16B per tile
            int row = idx >> 3, c = idx & 7;
            cpa16(smem_u32(qsm + st * 18432 + row * 144 + c * 16),
                  g_Xh + (size_t)(m0 + row) * 1024 + kb * 64 + c * 8);
            cpa16(smem_u32(qsm + 55296 + st * 18432 + row * 144 + c * 16),
                  W + (size_t)(n0 + row) * 1024 + kb * 64 + c * 8);
        }
    };

    float acc[4][4][4];
#pragma unroll
    for (int i = 0; i < 4; i++)
#pragma unroll
        for (int j = 0; j < 4; j++)
#pragma unroll
            for (int k = 0; k < 4; k++) acc[i][j][k] = 0.f;

    const uint32_t aOff = (uint32_t)(wm * 64 + (lane & 15)) * 144 + (lane >> 4) * 16;
    const uint32_t bOff = (uint32_t)(wn * 32 + (lane & 7) + ((lane >> 4) & 1) * 8) * 144
                        + ((lane >> 3) & 1) * 16;

    load_st(0, 0);
    CP_COMMIT();
    load_st(1, 1);
    CP_COMMIT();

    int st = 0;
    for (int kb = 0; kb < 16; kb++) {
        CP_WAIT(1);
        __syncthreads();
        if (kb + 2 < 16) load_st((kb + 2) % 3, kb + 2);
        CP_COMMIT();

        const uint32_t aAddr = smem_u32(qsm) + st * 18432 + aOff;
        const uint32_t bAddr = smem_u32(qsm) + 55296 + st * 18432 + bOff;
        st = (st == 2) ? 0 : st + 1;
#pragma unroll
        for (int kc = 0; kc < 4; kc++) {
            uint32_t a[4][4], b[2][4];
#pragma unroll
            for (int mt = 0; mt < 4; mt++) ldm4(a[mt], aAddr + kc * 32 + mt * 16 * 144);
#pragma unroll
            for (int np = 0; np < 2; np++) ldm4(b[np], bAddr + kc * 32 + np * 16 * 144);
#pragma unroll
            for (int mt = 0; mt < 4; mt++)
#pragma unroll
                for (int nt = 0; nt < 4; nt++)
                    mma16816(acc[mt][nt], a[mt], b[nt >> 1] + (nt & 1) * 2);
        }
    }

    // epilogue: bias + store into head-major scratch (fp16)
#pragma unroll
    for (int mt = 0; mt < 4; mt++) {
        int m  = m0 + wm * 64 + mt * 16 + (lane >> 2);
        int bb = m >> 11;
        int s  = m & 2047;
#pragma unroll
        for (int nt = 0; nt < 4; nt++) {
            int n  = n0 + wn * 32 + nt * 8 + (lane & 3) * 2;
            int h  = n >> 6, hd = n & 63;
            int bh = bb * 16 + h;
            float bs0 = bias[n], bs1 = bias[n + 1];
            float v00 = acc[mt][nt][0] + bs0, v01 = acc[mt][nt][1] + bs1;
            float v10 = acc[mt][nt][2] + bs0, v11 = acc[mt][nt][3] + bs1;
            if (z < 2) {
                __half* dst = (z == 0) ? g_Q : g_K;
                *(__half2*)&dst[((size_t)bh * 2048 + s    ) * 64 + hd] = __floats2half2_rn(v00, v01);
                *(__half2*)&dst[((size_t)bh * 2048 + s + 8) * 64 + hd] = __floats2half2_rn(v10, v11);
            } else {
                g_Vt[((size_t)bh * 64 + hd    ) * 2048 + s    ] = __float2half_rn(v00);
                g_Vt[((size_t)bh * 64 + hd + 1) * 2048 + s    ] = __float2half_rn(v01);
                g_Vt[((size_t)bh * 64 + hd    ) * 2048 + s + 8] = __float2half_rn(v10);
                g_Vt[((size_t)bh * 64 + hd + 1) * 2048 + s + 8] = __float2half_rn(v11);
            }
        }
    }
}

// ---------------- FlashAttention (fp16-accum score MMA, half2 softmax) ------
// R14 winner structure (128-key stages, smem mask, 4 warps x 32 q-rows,
// batched fragments) with the QK score MMA switched to fp16 accumulation
// (2x tensor rate, half the score registers) — the f16 C fragment is already
// packed in the ph half2 layout, so softmax is HFMA2 -> HMIN2 -> ex2.f16x2
// directly on the MMA output. PV MMA stays fp32-accum.
// smem layout (bytes):
//   Qs [128][72] half  : 0      .. 18432
//   Ks [2][128][72]    : 18432  .. 55296   (stage = 18432)
//   Vs [2][64][136]    : 55296  .. 90112   (stage = 17408, 272B rows)
//   maskH [2048] half  : 90112  .. 94208   (mask * LOG2E in fp16)
#define ATTN_SMEM 94208
__global__ __launch_bounds__(128, 2) void attn_kernel(const float* __restrict__ mask,
                                                      float* __restrict__ out) {
    extern __shared__ char sm[];
    __half (*Qs)[72] = (__half(*)[72])sm;
    char* ksBase = sm + 18432;
    char* vsBase = sm + 55296;
    __half* maskH = (__half*)(sm + 90112);

    const int bh = blockIdx.y;
    const int q0 = blockIdx.x * 128;
    const int b  = bh >> 4, h = bh & 15;
    const int t = threadIdx.x, warp = t >> 5, lane = t & 31;
    const __half2 clamp14 = __floats2half2_rn(14.f, 14.f);
    const __half2 scl2h = __floats2half2_rn(SCL, SCL);
    const uint32_t scl2 = *reinterpret_cast<const uint32_t*>(&scl2h);

    // stage loader: 128-key K tile (128x72h rows) + V^T tile (64x136h rows)
    auto load_kv = [&](int st, int k0) {
#pragma unroll
        for (int i = 0; i < 8; i++) {
            int idx = t + i * 128;           // K: 1024 chunks of 16B
            int row = idx >> 3, cb = idx & 7;
            cpa16(smem_u32(ksBase + st * 18432 + row * 144 + cb * 16),
                  &g_K[((size_t)bh * 2048 + k0 + row) * 64 + cb * 8]);
        }
#pragma unroll
        for (int i = 0; i < 8; i++) {
            int idx = t + i * 128;           // V: 1024 chunks of 16B
            int row = idx >> 4, cb = idx & 15;
            cpa16(smem_u32(vsBase + st * 17408 + row * 272 + cb * 16),
                  &g_Vt[((size_t)bh * 64 + row) * 2048 + k0 + cb * 8]);
        }
    };

    load_kv(0, 0);
    CP_COMMIT();

    // one-time mask preload (scaled by LOG2E, fp16)
#pragma unroll
    for (int i = 0; i < 16; i++)
        maskH[t + i * 128] = __float2half_rn(mask[b * 2048 + t + i * 128] * LOG2E);

#pragma unroll
    for (int i = 0; i < 8; i++) {
        int idx = t + i * 128;              // 1024 chunks for the 128x64 Q tile
        int row = idx >> 3, c8 = (idx & 7) * 8;
        *(uint4*)&Qs[row][c8] =
            *(const uint4*)&g_Q[((size_t)bh * 2048 + q0 + row) * 64 + c8];
    }
    __syncthreads();

    // Q fragments: 2 m-tiles x 4 k-chunks
    uint32_t qa[2][4][4];
#pragma unroll
    for (int mt = 0; mt < 2; mt++) {
        uint32_t qAddr = smem_u32(&Qs[warp * 32 + mt * 16 + (lane & 15)][(lane >> 4) * 8]);
#pragma unroll
        for (int ks = 0; ks < 4; ks++) ldm4(qa[mt][ks], qAddr + ks * 32);
    }

    const uint32_t kOff = ((lane & 7) + ((lane >> 4) & 1) * 8) * 144 + ((lane >> 3) & 1) * 16;
    const uint32_t vOff = ((lane & 7) + ((lane >> 4) & 1) * 8) * 272 + ((lane >> 3) & 1) * 16;
    const uint32_t kA0 = smem_u32(ksBase) + kOff;
    const uint32_t vA0 = smem_u32(vsBase) + vOff;

    float o[2][8][4];
#pragma unroll
    for (int mt = 0; mt < 2; mt++)
#pragma unroll
        for (int i = 0; i < 8; i++)
#pragma unroll
            for (int j = 0; j < 4; j++) o[mt][i][j] = 0.f;
    float l00 = 0.f, l01 = 0.f, l10 = 0.f, l11 = 0.f;

    for (int kt = 0; kt < 16; kt++) {
        CP_WAIT(0);                    // stage kt resident
        __syncthreads();               // stage kt-1 fully consumed by all warps
        if (kt + 1 < 16) load_kv((kt + 1) & 1, (kt + 1) * 128);
        CP_COMMIT();

        const int stg = kt & 1;
#pragma unroll
        for (int hh = 0; hh < 2; hh++) {
            const uint32_t kA = kA0 + stg * 18432 + hh * 64 * 144;
            const uint32_t vA = vA0 + stg * 17408 + hh * 128;   // 64 keys * 2B
            const __half* mk = maskH + kt * 128 + hh * 64;

            // scores (fp16 accum): 32 q-rows x 64 keys; sc[mt][nt] = 2 packed
            // half2 regs: [0] = row r (key pair), [1] = row r+8.
            uint32_t sc[2][8][2];
#pragma unroll
            for (int mt = 0; mt < 2; mt++)
#pragma unroll
                for (int nt = 0; nt < 8; nt++)
                    sc[mt][nt][0] = sc[mt][nt][1] = 0u;
#pragma unroll
            for (int ks = 0; ks < 4; ks++) {
                uint32_t kf[4][4];
#pragma unroll
                for (int np = 0; np < 4; np++)
                    ldm4(kf[np], kA + np * 16 * 144 + ks * 32);
#pragma unroll
                for (int np = 0; np < 4; np++)
#pragma unroll
                    for (int mt = 0; mt < 2; mt++) {
                        mma16816h(sc[mt][2*np    ], qa[mt][ks], kf[np]);
                        mma16816h(sc[mt][2*np + 1], qa[mt][ks], kf[np] + 2);
                    }
            }

            // chunk-interleaved softmax + PV; V fragments batched before the
            // softmax so the MUFU chain hides their latency
#pragma unroll
            for (int kc = 0; kc < 4; kc++) {
                uint32_t vf[4][4];
#pragma unroll
                for (int hp = 0; hp < 4; hp++)
                    ldm4(vf[hp], vA + hp * 16 * 272 + kc * 32);

                uint32_t ph[2][4];
#pragma unroll
                for (int mt = 0; mt < 2; mt++) {
                    float lp0 = 0.f, lp1 = 0.f;
#pragma unroll
                    for (int u = 0; u < 2; u++) {
                        int nt = 2 * kc + u;
                        int key = nt * 8 + (lane & 3) * 2;
                        uint32_t mk2 = *reinterpret_cast<const uint32_t*>(&mk[key]);
                        ph[mt][2*u    ] = softmax2(sc[mt][nt][0], scl2, mk2, clamp14);
                        ph[mt][2*u + 1] = softmax2(sc[mt][nt][1], scl2, mk2, clamp14);
                        float2 f0 = __half22float2(*reinterpret_cast<__half2*>(&ph[mt][2*u]));
                        float2 f1 = __half22float2(*reinterpret_cast<__half2*>(&ph[mt][2*u+1]));
                        lp0 += f0.x + f0.y;
                        lp1 += f1.x + f1.y;
                    }
                    if (mt == 0) { l00 += lp0; l01 += lp1; }
                    else         { l10 += lp0; l11 += lp1; }
                }
#pragma unroll
                for (int hp = 0; hp < 4; hp++)
#pragma unroll
                    for (int mt = 0; mt < 2; mt++) {
                        mma16816(o[mt][2*hp    ], ph[mt], vf[hp]);
                        mma16816(o[mt][2*hp + 1], ph[mt], vf[hp] + 2);
                    }
            }
        }
    }

    // epilogue: one cross-lane reduction, normalize, store fp32 [B,S,D]
    l00 += __shfl_xor_sync(0xffffffffu, l00, 1);
    l00 += __shfl_xor_sync(0xffffffffu, l00, 2);
    l01 += __shfl_xor_sync(0xffffffffu, l01, 1);
    l01 += __shfl_xor_sync(0xffffffffu, l01, 2);
    l10 += __shfl_xor_sync(0xffffffffu, l10, 1);
    l10 += __shfl_xor_sync(0xffffffffu, l10, 2);
    l11 += __shfl_xor_sync(0xffffffffu, l11, 1);
    l11 += __shfl_xor_sync(0xffffffffu, l11, 2);
    const int cb = h * 64 + (lane & 3) * 2;
#pragma unroll
    for (int mt = 0; mt < 2; mt++) {
        float rl0 = 1.f / (mt ? l10 : l00);
        float rl1 = 1.f / (mt ? l11 : l01);
        int s0 = q0 + warp * 32 + mt * 16 + (lane >> 2);
#pragma unroll
        for (int ht = 0; ht < 8; ht++) {
            int c = cb + ht * 8;
            float2 v0 = make_float2(o[mt][ht][0] * rl0, o[mt][ht][1] * rl0);
            float2 v1 = make_float2(o[mt][ht][2] * rl1, o[mt][ht][3] * rl1);
            *(float2*)&out[((size_t)b * 2048 + s0    ) * 1024 + c] = v0;
            *(float2*)&out[((size_t)b * 2048 + s0 + 8) * 1024 + c] = v1;
        }
    }
}

// ---------------- launch -----------------------------------------------------
extern "C" void kernel_launch(void* const* d_in, const int* in_sizes, int n_in,
                              void* d_out, int out_size) {
    const float* hidden = (const float*)d_in[0];
    const float* mask   = (const float*)d_in[1];
    const float* Wq     = (const float*)d_in[2];
    const float* bq     = (const float*)d_in[3];
    const float* Wk     = (const float*)d_in[4];
    const float* bk     = (const float*)d_in[5];
    const float* Wv     = (const float*)d_in[6];
    const float* bv     = (const float*)d_in[7];
    float* out = (float*)d_out;

    cudaFuncSetAttribute(qkv_gemm, cudaFuncAttributeMaxDynamicSharedMemorySize, QKV_SMEM);
    cudaFuncSetAttribute(attn_kernel, cudaFuncAttributeMaxDynamicSharedMemorySize, ATTN_SMEM);

    cvt_all<<<11264, 256>>>((const float4*)hidden, (const float4*)Wq,
                            (const float4*)Wk, (const float4*)Wv);

    dim3 g1(8, 64, 3);      // N-blocks, M-blocks, {Q,K,V}
    qkv_gemm<<<g1, 256, QKV_SMEM>>>(bq, bk, bv);

    dim3 g2(16, 64);        // q-tiles (128 rows), B*H
    attn_kernel<<<g2, 128, ATTN_SMEM>>>(mask, out);
}